// round 1
// baseline (speedup 1.0000x reference)
#include <cuda_runtime.h>
#include <math.h>

// Fixed problem dims (dataset is fixed; guarded by derived sizes at launch).
#define BDIM 8192
#define CDIM 2048
#define NW   8

// Precomputed half-angle cos/sin, transposed [wire][row] for coalesced tile loads.
__device__ float g_xc[NW * BDIM];
__device__ float g_xs[NW * BDIM];
__device__ float g_cc[NW * CDIM];
__device__ float g_cs[NW * CDIM];

__global__ void qk_precompute(const float* __restrict__ x,
                              const float* __restrict__ c,
                              int B, int C) {
    int idx = blockIdx.x * blockDim.x + threadIdx.x;
    int bx = B * NW;
    int total = bx + C * NW;
    if (idx >= total) return;
    if (idx < bx) {
        int row = idx >> 3, j = idx & 7;
        float s, co;
        sincosf(0.5f * x[row * NW + j], &s, &co);
        g_xc[j * B + row] = co;
        g_xs[j * B + row] = s;
    } else {
        int t = idx - bx;
        int row = t >> 3, j = t & 7;
        float s, co;
        sincosf(0.5f * c[row * NW + j], &s, &co);
        g_cc[j * C + row] = co;
        g_cs[j * C + row] = s;
    }
}

// Block tile: 128 rows (x) x 128 cols (centers). 256 threads.
// Thread tile: 8 rows x 8 cols, cols held as 4 packed f32x2 column-pairs
// at columns {2*tx, 2*tx+1} + 32*cp  (cp = 0..3) -> conflict-free LDS.64.
__global__ void __launch_bounds__(256, 2)
qk_fidelity(float* __restrict__ out, int B, int C) {
    __shared__ __align__(16) float sxc[NW][128];
    __shared__ __align__(16) float sxs[NW][128];
    __shared__ __align__(16) float scc[NW][128];
    __shared__ __align__(16) float scs[NW][128];

    const int row0 = blockIdx.y * 128;
    const int col0 = blockIdx.x * 128;
    const int tid = threadIdx.x;

    // Cooperative tile load: 8 wires x 128 values per array.
    #pragma unroll
    for (int it = 0; it < 4; it++) {
        int idx = tid + it * 256;
        int j = idx >> 7, r = idx & 127;
        sxc[j][r] = g_xc[j * B + row0 + r];
        sxs[j][r] = g_xs[j * B + row0 + r];
        scc[j][r] = g_cc[j * C + col0 + r];
        scs[j][r] = g_cs[j * C + col0 + r];
    }
    __syncthreads();

    const int ty = tid >> 4;      // 0..15 -> row group
    const int tx = tid & 15;      // 0..15 -> column-pair lane
    const int rbase = ty * 8;

    unsigned long long prod[8][4];

    #pragma unroll
    for (int j = 0; j < NW; j++) {
        // b operands: 4 column-pairs, contiguous across tx (conflict-free LDS.64)
        unsigned long long bc[4], bs[4];
        #pragma unroll
        for (int cp = 0; cp < 4; cp++) {
            bc[cp] = *(const unsigned long long*)&scc[j][2 * tx + 32 * cp];
            bs[cp] = *(const unsigned long long*)&scs[j][2 * tx + 32 * cp];
        }
        #pragma unroll
        for (int r = 0; r < 8; r++) {
            unsigned int fc = __float_as_uint(sxc[j][rbase + r]);
            unsigned int fs = __float_as_uint(sxs[j][rbase + r]);
            unsigned long long ac, as;
            asm("mov.b64 %0, {%1, %1};" : "=l"(ac) : "r"(fc));
            asm("mov.b64 %0, {%1, %1};" : "=l"(as) : "r"(fs));
            #pragma unroll
            for (int cp = 0; cp < 4; cp++) {
                unsigned long long t;
                asm("mul.rn.f32x2 %0, %1, %2;" : "=l"(t) : "l"(ac), "l"(bc[cp]));
                asm("fma.rn.f32x2 %0, %1, %2, %3;" : "=l"(t) : "l"(as), "l"(bs[cp]), "l"(t));
                if (j == 0) {
                    prod[r][cp] = t;
                } else {
                    asm("mul.rn.f32x2 %0, %1, %2;"
                        : "=l"(prod[r][cp]) : "l"(prod[r][cp]), "l"(t));
                }
            }
        }
    }

    // Epilogue: |value| via sign-bit mask on the packed pair, STG.64 stores.
    #pragma unroll
    for (int r = 0; r < 8; r++) {
        float* orow = out + (size_t)(row0 + rbase + r) * C + col0 + 2 * tx;
        #pragma unroll
        for (int cp = 0; cp < 4; cp++) {
            unsigned long long v = prod[r][cp] & 0x7FFFFFFF7FFFFFFFull;
            *(unsigned long long*)(orow + 32 * cp) = v;
        }
    }
}

extern "C" void kernel_launch(void* const* d_in, const int* in_sizes, int n_in,
                              void* d_out, int out_size) {
    const float* x = (const float*)d_in[0];
    const float* c = (const float*)d_in[1];
    float* out = (float*)d_out;

    int B = in_sizes[0] / NW;   // 8192
    int C = in_sizes[1] / NW;   // 2048
    if (B > BDIM) B = BDIM;
    if (C > CDIM) C = CDIM;

    int total = (B + C) * NW;
    qk_precompute<<<(total + 255) / 256, 256>>>(x, c, B, C);

    dim3 grid(C / 128, B / 128);
    qk_fidelity<<<grid, 256>>>(out, B, C);
}